// round 6
// baseline (speedup 1.0000x reference)
#include <cuda_runtime.h>
#include <cuda_bf16.h>
#include <cstdint>

// FM-CTR kernel — R6: cp.async (LDGSTS) staged gathers for guaranteed MLP=26.
// Inputs (metadata order):
//  d_in[0]: dense_x     f32 [16384, 13]
//  d_in[1]: discrete_x  i32 [16384, 26]
//  d_in[2]: emb_tables  f32 [26, 50000, 128]
//  d_in[3]: dense_w     f32 [128, 13]
//  d_in[4]: dense_b     f32 [128]
// Output: f32 [16384]
//
// 1 warp per row; lane l owns float4 slice [4l,4l+4). Each lane issues 26
// cp.async.cg 16B copies (register-free, unserializable by ptxas -> true
// 26-deep memory pipeline), computes the dense matvec under the shadow,
// waits, then consumes ITS OWN staged bytes (no cross-thread sharing ->
// no block/warp barrier needed).

#define N_TABLES 26
#define VOCAB    50000
#define EMBED_DIM 128
#define DENSE_DIM 13
#define BATCH    16384
#define WARPS_PER_BLOCK 8
#define THREADS (WARPS_PER_BLOCK * 32)
// per-warp staging: 26 tables * 32 lanes * 16B = 13312 B
#define SMEM_PER_WARP (N_TABLES * 32 * 16)
#define SMEM_BYTES (WARPS_PER_BLOCK * SMEM_PER_WARP)

__device__ __forceinline__ void cp_async16(void* smem_dst, const void* gmem_src)
{
    unsigned int saddr = (unsigned int)__cvta_generic_to_shared(smem_dst);
    asm volatile("cp.async.cg.shared.global [%0], [%1], 16;\n"
                 :: "r"(saddr), "l"(gmem_src));
}

__global__ __launch_bounds__(THREADS) void fm_ctr_kernel(
    const float* __restrict__ dense_x,
    const int*   __restrict__ discrete_x,
    const float* __restrict__ emb,
    const float* __restrict__ dense_w,
    const float* __restrict__ dense_b,
    float* __restrict__ out)
{
    extern __shared__ __align__(16) char smem_raw[];

    const int warp_in_blk = threadIdx.x >> 5;
    const int lane  = threadIdx.x & 31;
    const int gwarp = blockIdx.x * WARPS_PER_BLOCK + warp_in_blk;
    if (gwarp >= BATCH) return;

    // my 16B landing slot for table t:
    char* my_slot0 = smem_raw + (size_t)warp_in_blk * SMEM_PER_WARP + lane * 16;

    // Lanes 0..25 load one index each; broadcast via shfl.
    int my_idx = 0;
    if (lane < N_TABLES)
        my_idx = discrete_x[(long long)gwarp * N_TABLES + lane];

    // ---- Issue all 26 gathers (register-free async pipeline) ----
    #pragma unroll
    for (int t = 0; t < N_TABLES; t++) {
        int id = __shfl_sync(0xffffffffu, my_idx, t);
        const float* src = emb + ((long long)t * VOCAB + (long long)id) * EMBED_DIM
                               + lane * 4;
        cp_async16(my_slot0 + (size_t)t * (32 * 16), src);
    }
    asm volatile("cp.async.commit_group;\n" ::: "memory");

    // ---- Dense matvec under the shadow of the in-flight gathers ----
    float xr[DENSE_DIM];
    #pragma unroll
    for (int k = 0; k < DENSE_DIM; k++)
        xr[k] = __ldg(dense_x + (long long)gwarp * DENSE_DIM + k);

    float e0 = __ldg(dense_b + 4 * lane + 0);
    float e1 = __ldg(dense_b + 4 * lane + 1);
    float e2 = __ldg(dense_b + 4 * lane + 2);
    float e3 = __ldg(dense_b + 4 * lane + 3);
    #pragma unroll
    for (int k = 0; k < DENSE_DIM; k++) {
        e0 = fmaf(xr[k], __ldg(dense_w + (4 * lane + 0) * DENSE_DIM + k), e0);
        e1 = fmaf(xr[k], __ldg(dense_w + (4 * lane + 1) * DENSE_DIM + k), e1);
        e2 = fmaf(xr[k], __ldg(dense_w + (4 * lane + 2) * DENSE_DIM + k), e2);
        e3 = fmaf(xr[k], __ldg(dense_w + (4 * lane + 3) * DENSE_DIM + k), e3);
    }

    float4 s = make_float4(e0, e1, e2, e3);
    float4 q;
    q.x = e0 * e0; q.y = e1 * e1; q.z = e2 * e2; q.w = e3 * e3;

    // ---- Wait for gathers; consume my own staged bytes (no barrier needed) ----
    asm volatile("cp.async.wait_group 0;\n" ::: "memory");

    #pragma unroll
    for (int t = 0; t < N_TABLES; t++) {
        float4 v = *reinterpret_cast<const float4*>(my_slot0 + (size_t)t * (32 * 16));
        s.x += v.x; s.y += v.y; s.z += v.z; s.w += v.w;
        q.x = fmaf(v.x, v.x, q.x);
        q.y = fmaf(v.y, v.y, q.y);
        q.z = fmaf(v.z, v.z, q.z);
        q.w = fmaf(v.w, v.w, q.w);
    }

    // FM partial for my 4 dims: 0.5 * (S^2 - sumsq)
    float fm = 0.5f * ((s.x * s.x - q.x) + (s.y * s.y - q.y) +
                       (s.z * s.z - q.z) + (s.w * s.w - q.w));

    // Warp reduction.
    #pragma unroll
    for (int o = 16; o > 0; o >>= 1)
        fm += __shfl_down_sync(0xffffffffu, fm, o);

    if (lane == 0) out[gwarp] = fm;
}

extern "C" void kernel_launch(void* const* d_in, const int* in_sizes, int n_in,
                              void* d_out, int out_size)
{
    const float* dense_x    = (const float*)d_in[0];
    const int*   discrete_x = (const int*)d_in[1];
    const float* emb        = (const float*)d_in[2];
    const float* dense_w    = (const float*)d_in[3];
    const float* dense_b    = (const float*)d_in[4];
    float* out = (float*)d_out;

    static bool attr_done = false;
    if (!attr_done) {
        cudaFuncSetAttribute(fm_ctr_kernel,
                             cudaFuncAttributeMaxDynamicSharedMemorySize,
                             SMEM_BYTES);
        attr_done = true;
    }

    const int blocks = (BATCH + WARPS_PER_BLOCK - 1) / WARPS_PER_BLOCK;
    fm_ctr_kernel<<<blocks, THREADS, SMEM_BYTES>>>(dense_x, discrete_x, emb,
                                                   dense_w, dense_b, out);
}

// round 9
// speedup vs baseline: 1.0801x; 1.0801x over previous
#include <cuda_runtime.h>
#include <cuda_bf16.h>
#include <cstdint>

// FM-CTR kernel — R9: hybrid cp.async(12 tables) + rolling LDG(14 tables).
// Inputs (metadata order):
//  d_in[0]: dense_x     f32 [16384, 13]
//  d_in[1]: discrete_x  i32 [16384, 26]
//  d_in[2]: emb_tables  f32 [26, 50000, 128]
//  d_in[3]: dense_w     f32 [128, 13]
//  d_in[4]: dense_b     f32 [128]
// Output: f32 [16384]
//
// 1 warp per row; lane l owns float4 slice [4l,4l+4).
// Tables 14..25: staged via cp.async (register-free, guaranteed 12-deep).
// Tables 0..13:  rolling LDG consumed while the asyncs fly.
// Dense matvec also under the async shadow.
// smem = 6KB/warp -> 48KB/block exactly (no cudaFuncSetAttribute needed,
// kernel_launch is a single pure kernel launch) -> 4 blocks/SM, occ ~50%.

#define N_TABLES 26
#define VOCAB    50000
#define EMBED_DIM 128
#define DENSE_DIM 13
#define BATCH    16384
#define WARPS_PER_BLOCK 8
#define THREADS (WARPS_PER_BLOCK * 32)
#define N_ASYNC  12                      // tables 14..25 staged in smem
#define N_DIRECT 14                      // tables 0..13 via LDG
#define SMEM_PER_WARP (N_ASYNC * 32 * 16)             // 6144 B
#define SMEM_BYTES (WARPS_PER_BLOCK * SMEM_PER_WARP)  // 49152 B == 48KB default cap

__device__ __forceinline__ void cp_async16(void* smem_dst, const void* gmem_src)
{
    unsigned int saddr = (unsigned int)__cvta_generic_to_shared(smem_dst);
    asm volatile("cp.async.cg.shared.global [%0], [%1], 16;\n"
                 :: "r"(saddr), "l"(gmem_src));
}

__global__ __launch_bounds__(THREADS) void fm_ctr_kernel(
    const float* __restrict__ dense_x,
    const int*   __restrict__ discrete_x,
    const float* __restrict__ emb,
    const float* __restrict__ dense_w,
    const float* __restrict__ dense_b,
    float* __restrict__ out)
{
    extern __shared__ __align__(16) char smem_raw[];

    const int warp_in_blk = threadIdx.x >> 5;
    const int lane  = threadIdx.x & 31;
    const int gwarp = blockIdx.x * WARPS_PER_BLOCK + warp_in_blk;
    if (gwarp >= BATCH) return;

    char* my_slot0 = smem_raw + (size_t)warp_in_blk * SMEM_PER_WARP + lane * 16;

    // Lanes 0..25 load one index each; broadcast via shfl.
    int my_idx = 0;
    if (lane < N_TABLES)
        my_idx = discrete_x[(long long)gwarp * N_TABLES + lane];

    // ---- Phase 1: fire 12 async gathers for tables 14..25 (no registers) ----
    #pragma unroll
    for (int a = 0; a < N_ASYNC; a++) {
        int t = N_DIRECT + a;
        int id = __shfl_sync(0xffffffffu, my_idx, t);
        const float* src = emb + ((long long)t * VOCAB + (long long)id) * EMBED_DIM
                               + lane * 4;
        cp_async16(my_slot0 + (size_t)a * (32 * 16), src);
    }
    asm volatile("cp.async.commit_group;\n" ::: "memory");

    float4 s = make_float4(0.f, 0.f, 0.f, 0.f);
    float4 q = make_float4(0.f, 0.f, 0.f, 0.f);

    // ---- Phase 2: rolling LDG over tables 0..13 while asyncs fly ----
    #pragma unroll
    for (int t = 0; t < N_DIRECT; t++) {
        int id = __shfl_sync(0xffffffffu, my_idx, t);
        const float4* row = reinterpret_cast<const float4*>(
            emb + ((long long)t * VOCAB + (long long)id) * EMBED_DIM);
        float4 v = __ldg(row + lane);
        s.x += v.x; s.y += v.y; s.z += v.z; s.w += v.w;
        q.x = fmaf(v.x, v.x, q.x);
        q.y = fmaf(v.y, v.y, q.y);
        q.z = fmaf(v.z, v.z, q.z);
        q.w = fmaf(v.w, v.w, q.w);
    }

    // ---- Phase 3: dense matvec, still under the async shadow ----
    float xr[DENSE_DIM];
    #pragma unroll
    for (int k = 0; k < DENSE_DIM; k++)
        xr[k] = __ldg(dense_x + (long long)gwarp * DENSE_DIM + k);

    float e0 = __ldg(dense_b + 4 * lane + 0);
    float e1 = __ldg(dense_b + 4 * lane + 1);
    float e2 = __ldg(dense_b + 4 * lane + 2);
    float e3 = __ldg(dense_b + 4 * lane + 3);
    #pragma unroll
    for (int k = 0; k < DENSE_DIM; k++) {
        e0 = fmaf(xr[k], __ldg(dense_w + (4 * lane + 0) * DENSE_DIM + k), e0);
        e1 = fmaf(xr[k], __ldg(dense_w + (4 * lane + 1) * DENSE_DIM + k), e1);
        e2 = fmaf(xr[k], __ldg(dense_w + (4 * lane + 2) * DENSE_DIM + k), e2);
        e3 = fmaf(xr[k], __ldg(dense_w + (4 * lane + 3) * DENSE_DIM + k), e3);
    }
    s.x += e0; q.x = fmaf(e0, e0, q.x);
    s.y += e1; q.y = fmaf(e1, e1, q.y);
    s.z += e2; q.z = fmaf(e2, e2, q.z);
    s.w += e3; q.w = fmaf(e3, e3, q.w);

    // ---- Phase 4: drain the async group; consume own staged bytes ----
    asm volatile("cp.async.wait_group 0;\n" ::: "memory");

    #pragma unroll
    for (int a = 0; a < N_ASYNC; a++) {
        float4 v = *reinterpret_cast<const float4*>(my_slot0 + (size_t)a * (32 * 16));
        s.x += v.x; s.y += v.y; s.z += v.z; s.w += v.w;
        q.x = fmaf(v.x, v.x, q.x);
        q.y = fmaf(v.y, v.y, q.y);
        q.z = fmaf(v.z, v.z, q.z);
        q.w = fmaf(v.w, v.w, q.w);
    }

    // FM partial for my 4 dims: 0.5 * (S^2 - sumsq)
    float fm = 0.5f * ((s.x * s.x - q.x) + (s.y * s.y - q.y) +
                       (s.z * s.z - q.z) + (s.w * s.w - q.w));

    #pragma unroll
    for (int o = 16; o > 0; o >>= 1)
        fm += __shfl_down_sync(0xffffffffu, fm, o);

    if (lane == 0) out[gwarp] = fm;
}

extern "C" void kernel_launch(void* const* d_in, const int* in_sizes, int n_in,
                              void* d_out, int out_size)
{
    const float* dense_x    = (const float*)d_in[0];
    const int*   discrete_x = (const int*)d_in[1];
    const float* emb        = (const float*)d_in[2];
    const float* dense_w    = (const float*)d_in[3];
    const float* dense_b    = (const float*)d_in[4];
    float* out = (float*)d_out;

    const int blocks = (BATCH + WARPS_PER_BLOCK - 1) / WARPS_PER_BLOCK;
    fm_ctr_kernel<<<blocks, THREADS, SMEM_BYTES>>>(dense_x, discrete_x, emb,
                                                   dense_w, dense_b, out);
}

// round 10
// speedup vs baseline: 1.1301x; 1.0463x over previous
#include <cuda_runtime.h>
#include <cuda_bf16.h>
#include <cstdint>

// FM-CTR kernel — R10: pure-LDG rolling gathers at max occupancy.
// Evidence from R5/R6/R9: DRAM% tracks warp count, not per-warp pipeline
// depth. So: no smem, no cp.async, 32-reg budget -> 8 blocks/SM (100% occ).
//
// Inputs (metadata order):
//  d_in[0]: dense_x     f32 [16384, 13]
//  d_in[1]: discrete_x  i32 [16384, 26]
//  d_in[2]: emb_tables  f32 [26, 50000, 128]
//  d_in[3]: dense_w     f32 [128, 13]
//  d_in[4]: dense_b     f32 [128]
// Output: f32 [16384]
//
// 1 warp per row; lane l owns float4 slice [4l,4l+4); each table gather is
// one coalesced 512B warp read. Dense matvec is computed FIRST so its
// registers (xr[13], e0..e3) are dead during the gather loop, keeping the
// loop's live set tiny. 32-bit offset math (max offset 166.4M elems < 2^31).

#define N_TABLES 26
#define VOCAB    50000
#define EMBED_DIM 128
#define DENSE_DIM 13
#define BATCH    16384

__global__ __launch_bounds__(256, 8) void fm_ctr_kernel(
    const float* __restrict__ dense_x,
    const int*   __restrict__ discrete_x,
    const float* __restrict__ emb,
    const float* __restrict__ dense_w,
    const float* __restrict__ dense_b,
    float* __restrict__ out)
{
    const int gwarp = (blockIdx.x * blockDim.x + threadIdx.x) >> 5;
    const int lane  = threadIdx.x & 31;
    if (gwarp >= BATCH) return;

    // Lanes 0..25 load one index each; broadcast below via shfl.
    int my_idx = 0;
    if (lane < N_TABLES)
        my_idx = discrete_x[gwarp * N_TABLES + lane];

    // ---- Dense matvec first (registers die before the gather loop) ----
    // e[d] = sum_k dense_x[b,k]*dense_w[d,k] + dense_b[d]; lane owns d=4l..4l+3
    float4 s, q;
    {
        float xr[DENSE_DIM];
        #pragma unroll
        for (int k = 0; k < DENSE_DIM; k++)
            xr[k] = __ldg(dense_x + gwarp * DENSE_DIM + k);

        float e0 = __ldg(dense_b + 4 * lane + 0);
        float e1 = __ldg(dense_b + 4 * lane + 1);
        float e2 = __ldg(dense_b + 4 * lane + 2);
        float e3 = __ldg(dense_b + 4 * lane + 3);
        #pragma unroll
        for (int k = 0; k < DENSE_DIM; k++) {
            e0 = fmaf(xr[k], __ldg(dense_w + (4 * lane + 0) * DENSE_DIM + k), e0);
            e1 = fmaf(xr[k], __ldg(dense_w + (4 * lane + 1) * DENSE_DIM + k), e1);
            e2 = fmaf(xr[k], __ldg(dense_w + (4 * lane + 2) * DENSE_DIM + k), e2);
            e3 = fmaf(xr[k], __ldg(dense_w + (4 * lane + 3) * DENSE_DIM + k), e3);
        }
        s = make_float4(e0, e1, e2, e3);
        q = make_float4(e0 * e0, e1 * e1, e2 * e2, e3 * e3);
    }

    // ---- Rolling gathers over all 26 tables (32-bit offsets) ----
    #pragma unroll
    for (int t = 0; t < N_TABLES; t++) {
        int id = __shfl_sync(0xffffffffu, my_idx, t);
        // element offset fits in 32 bits: max 26*50000*128 = 166.4M < 2^31
        unsigned off = (unsigned)(t * VOCAB * EMBED_DIM) + ((unsigned)id << 7);
        float4 v = __ldg(reinterpret_cast<const float4*>(emb + off) + lane);
        s.x += v.x; s.y += v.y; s.z += v.z; s.w += v.w;
        q.x = fmaf(v.x, v.x, q.x);
        q.y = fmaf(v.y, v.y, q.y);
        q.z = fmaf(v.z, v.z, q.z);
        q.w = fmaf(v.w, v.w, q.w);
    }

    // FM partial for my 4 dims: 0.5 * (S^2 - sumsq)
    float fm = 0.5f * ((s.x * s.x - q.x) + (s.y * s.y - q.y) +
                       (s.z * s.z - q.z) + (s.w * s.w - q.w));

    // Warp reduction.
    #pragma unroll
    for (int o = 16; o > 0; o >>= 1)
        fm += __shfl_down_sync(0xffffffffu, fm, o);

    if (lane == 0) out[gwarp] = fm;
}

extern "C" void kernel_launch(void* const* d_in, const int* in_sizes, int n_in,
                              void* d_out, int out_size)
{
    const float* dense_x    = (const float*)d_in[0];
    const int*   discrete_x = (const int*)d_in[1];
    const float* emb        = (const float*)d_in[2];
    const float* dense_w    = (const float*)d_in[3];
    const float* dense_b    = (const float*)d_in[4];
    float* out = (float*)d_out;

    const int threads = 256;                 // 8 warps / block
    const int rows_per_block = threads / 32;
    const int blocks = (BATCH + rows_per_block - 1) / rows_per_block;
    fm_ctr_kernel<<<blocks, threads>>>(dense_x, discrete_x, emb,
                                       dense_w, dense_b, out);
}